// round 16
// baseline (speedup 1.0000x reference)
#include <cuda_runtime.h>
#include <cuda_fp16.h>
#include <math.h>
#include <stdint.h>

#define K_CODES 1024
#define D_DIM   256
#define N_ROWS  131072

#define FLAG_THRESH  2.0f      // f16-acc dist-err std ~0.1 -> >=10 sigma
#define RESCUE_RPB   8

// ---------------- scratch (device globals; no allocations allowed) ----------
__device__ float        d_cnorm[K_CODES];            // emulated sum(e*e)
__device__ float        d_embedT[K_CODES * D_DIM];   // fp32 codebook, k-major
__device__ uint32_t     d_eBh2[32 * 4096];           // fp16x2 B chunks
__device__ unsigned int d_counts[K_CODES];
__device__ float        d_loss_partial[1024];
__device__ int          d_nflag;
__device__ int          d_flaglist[N_ROWS];

__device__ __forceinline__ uint32_t pack_h2(float a, float b) {
    __half2 h = __floats2half2_rn(a, b);
    return *(uint32_t*)&h;
}

// ---------------------------------------------------------------------------
// Prep 1: emulated codebook norms (ascending-d, mul-then-add), fp32 transpose
// ---------------------------------------------------------------------------
__global__ void vq_prep(const float* __restrict__ embed) {
    int k = blockIdx.x * blockDim.x + threadIdx.x;  // 0..1023
    float s = 0.0f;
    for (int d = 0; d < D_DIM; ++d) {
        float v = embed[(size_t)d * K_CODES + k];
        s = __fadd_rn(s, __fmul_rn(v, v));
        d_embedT[(size_t)k * D_DIM + d] = v;
    }
    d_cnorm[k]  = s;
    d_counts[k] = 0u;
    if (k == 0) d_nflag = 0;
}

// ---------------------------------------------------------------------------
// Prep 2: fp16x2 B chunks: chunk cidx = cb*8 + dc holds
//   [dl 0..31][j 0..127] = h2(E[dc*32+dl][cb*256+2j], E[..][2j+1])
// ---------------------------------------------------------------------------
__global__ void vq_prep_frag16(const float* __restrict__ embed) {
    const int cidx = blockIdx.x;       // 0..31
    const int cb = cidx >> 3, dc = cidx & 7;
    #pragma unroll
    for (int q = 0; q < 16; ++q) {
        int p  = q * 256 + threadIdx.x;    // 0..4095
        int dl = p >> 7, j = p & 127;
        int d  = dc * 32 + dl;
        int c0 = cb * 256 + 2 * j;
        float v0 = embed[(size_t)d * K_CODES + c0];
        float v1 = embed[(size_t)d * K_CODES + c0 + 1];
        d_eBh2[(size_t)cidx * 4096 + p] = pack_h2(v0, v1);
    }
}

// ---------------------------------------------------------------------------
// SMEM layout (bytes):
//   [0,4224)        sCnP  (1056 f32, stride-33 padded cnorm)
//   [4224,4736)     sIdx  (128 int)
//   [4736,4800)     sRed
//   [4800,70848)    sAh   (128 d2 x 129 u32; h2(x[2d],x[2d+1]) per row)
//   [70848,103616)  sBh   (2 bufs x 4096 u32 = one chunk each)
// 103.6KB/CTA -> 2 CTAs/SM
// ---------------------------------------------------------------------------
#define SM_CN   0
#define SM_IDX  4224
#define SM_RED  4736
#define SM_AH   4800
#define SM_BH   70848
#define SMEM_TOTAL 103616

__device__ __forceinline__ void top2_upd(float& v1, float& v2, int& i1,
                                         float d, int code) {
    if (d < v1)      { v2 = v1; v1 = d; i1 = code; }
    else if (d < v2) { v2 = d; }
}

__global__ void __launch_bounds__(256, 2)
vq_main_hf(const float* __restrict__ inputs, float* __restrict__ out) {
    extern __shared__ char smem[];
    float*    sCnP = (float*)(smem + SM_CN);
    int*      sIdx = (int*)(smem + SM_IDX);
    float*    sRed = (float*)(smem + SM_RED);
    uint32_t* sAh  = (uint32_t*)(smem + SM_AH);
    uint32_t* sBh  = (uint32_t*)(smem + SM_BH);

    const int t    = threadIdx.x;
    const int w    = t >> 5;
    const int lane = t & 31;
    const int r4   = lane & 3;
    const int c8   = lane >> 2;
    const int row0 = blockIdx.x * 128;

    for (int i = t; i < K_CODES; i += 256)
        sCnP[i + (i >> 5)] = d_cnorm[i];

    // ---- Stage A: [d2][row] fp16x2, 129-pad (2-way STS, conflict-free LDS)
    {
        const float4* in4 = (const float4*)(inputs + (size_t)row0 * D_DIM);
        #pragma unroll
        for (int i = 0; i < 32; ++i) {
            int l   = i * 256 + t;
            int row = l >> 6;
            int d4  = l & 63;
            float4 v = in4[row * 64 + d4];
            sAh[(2 * d4) * 129 + row]     = pack_h2(v.x, v.y);
            sAh[(2 * d4 + 1) * 129 + row] = pack_h2(v.z, v.w);
        }
    }

    // ---- Prefetch + stage B chunk 0 ----
    uint4 pv[4];
    {
        const uint4* src = (const uint4*)d_eBh2;
        uint4* dst = (uint4*)sBh;
        #pragma unroll
        for (int q = 0; q < 4; ++q) {
            pv[q] = src[q * 256 + t];
            dst[q * 256 + t] = pv[q];
        }
    }
    __syncthreads();

    const __half2 hz = __floats2half2_rn(0.0f, 0.0f);
    __half2 acc[4][16];
    #pragma unroll
    for (int i = 0; i < 4; ++i)
        #pragma unroll
        for (int c = 0; c < 16; ++c) acc[i][c] = hz;

    float v1[4], v2[4]; int i1[4];
    #pragma unroll
    for (int i = 0; i < 4; ++i) { v1[i] = 3.4e38f; v2[i] = 3.4e38f; i1[i] = 0; }

    const int abase = w * 16 + r4;   // + i*4 + d2*129

    for (int cidx = 0; cidx < 32; ++cidx) {     // cidx = cb*8 + dc
        if (cidx < 31) {
            const uint4* src = (const uint4*)(d_eBh2 + (size_t)(cidx + 1) * 4096);
            #pragma unroll
            for (int q = 0; q < 4; ++q) pv[q] = src[q * 256 + t];
        }

        const uint32_t* bb = sBh + (cidx & 1) * 4096 + c8 * 16;
        const uint32_t* aB = sAh + (cidx & 7) * 16 * 129 + abase;

        #pragma unroll
        for (int d2l = 0; d2l < 16; ++d2l) {
            uint32_t a_raw[4];
            #pragma unroll
            for (int i = 0; i < 4; ++i)
                a_raw[i] = aB[d2l * 129 + i * 4];
            #pragma unroll
            for (int h = 0; h < 2; ++h) {
                const uint32_t* bp = bb + (2 * d2l + h) * 128;
                uint4 b0 = *(const uint4*)(bp);
                uint4 b1 = *(const uint4*)(bp + 4);
                uint4 b2 = *(const uint4*)(bp + 8);
                uint4 b3 = *(const uint4*)(bp + 12);
                __half2 bh[16];
                bh[0]  = *(__half2*)&b0.x;  bh[1]  = *(__half2*)&b0.y;
                bh[2]  = *(__half2*)&b0.z;  bh[3]  = *(__half2*)&b0.w;
                bh[4]  = *(__half2*)&b1.x;  bh[5]  = *(__half2*)&b1.y;
                bh[6]  = *(__half2*)&b1.z;  bh[7]  = *(__half2*)&b1.w;
                bh[8]  = *(__half2*)&b2.x;  bh[9]  = *(__half2*)&b2.y;
                bh[10] = *(__half2*)&b2.z;  bh[11] = *(__half2*)&b2.w;
                bh[12] = *(__half2*)&b3.x;  bh[13] = *(__half2*)&b3.y;
                bh[14] = *(__half2*)&b3.z;  bh[15] = *(__half2*)&b3.w;
                #pragma unroll
                for (int i = 0; i < 4; ++i) {
                    __half2 ah2 = *(__half2*)&a_raw[i];
                    __half2 a = h ? __high2half2(ah2) : __low2half2(ah2);
                    #pragma unroll
                    for (int c = 0; c < 16; ++c)
                        acc[i][c] = __hfma2(a, bh[c], acc[i][c]);
                }
            }
        }

        // epilogue at end of each cb (8 chunks)
        if ((cidx & 7) == 7) {
            int cb = cidx >> 3;
            int cbase = cb * 256 + c8 * 32;
            int pbase = cbase + cb * 8 + c8;     // padded cnorm index
            #pragma unroll
            for (int i = 0; i < 4; ++i) {
                #pragma unroll
                for (int c = 0; c < 16; ++c) {
                    float2 f = __half22float2(acc[i][c]);
                    float d0 = sCnP[pbase + 2 * c]     - 2.0f * f.x;
                    float d1 = sCnP[pbase + 2 * c + 1] - 2.0f * f.y;
                    top2_upd(v1[i], v2[i], i1[i], d0, cbase + 2 * c);
                    top2_upd(v1[i], v2[i], i1[i], d1, cbase + 2 * c + 1);
                    acc[i][c] = hz;
                }
            }
        }

        if (cidx < 31) {
            uint4* dst = (uint4*)(sBh + ((cidx + 1) & 1) * 4096);
            #pragma unroll
            for (int q = 0; q < 4; ++q) dst[q * 256 + t] = pv[q];
        }
        __syncthreads();
    }

    // ---- merge top-2 across the 8 c8-lanes sharing each row ----
    #pragma unroll
    for (int off = 4; off < 32; off <<= 1) {
        #pragma unroll
        for (int i = 0; i < 4; ++i) {
            float w1 = __shfl_down_sync(0xffffffffu, v1[i], off, 32);
            int   wi = __shfl_down_sync(0xffffffffu, i1[i], off, 32);
            float w2 = __shfl_down_sync(0xffffffffu, v2[i], off, 32);
            if (w1 < v1[i] || (w1 == v1[i] && wi < i1[i])) {
                v2[i] = fminf(v1[i], w2); v1[i] = w1; i1[i] = wi;
            } else v2[i] = fminf(v2[i], w1);
        }
    }

    const size_t ND = (size_t)N_ROWS * D_DIM;
    if (lane < 4) {
        #pragma unroll
        for (int i = 0; i < 4; ++i) {
            int row = w * 16 + i * 4 + r4;
            sIdx[row] = i1[i];
            if (v2[i] - v1[i] < FLAG_THRESH) {
                int pos = atomicAdd(&d_nflag, 1);
                d_flaglist[pos] = row0 + row;
            }
            atomicAdd(&d_counts[i1[i]], 1u);
            out[ND + 2 + (size_t)(row0 + row)] = (float)i1[i];
        }
    }
    __syncthreads();

    // ---- quantize (= q exactly) + loss partials ----
    float lsum = 0.0f;
    const float4* inp4 = (const float4*)(inputs + (size_t)row0 * D_DIM);
    float4*       out4 = (float4*)(out + (size_t)row0 * D_DIM);
    const float4* eT4  = (const float4*)d_embedT;
    #pragma unroll 4
    for (int it = 0; it < 32; ++it) {
        int l  = it * 256 + t;
        int r  = l >> 6;
        int d4 = l & 63;
        float4 x = inp4[r * 64 + d4];
        int    k = sIdx[r];
        float4 q = eT4[(size_t)k * 64 + d4];
        float dx = q.x - x.x, dy = q.y - x.y, dz = q.z - x.z, dw = q.w - x.w;
        lsum += dx * dx + dy * dy + dz * dz + dw * dw;
        out4[r * 64 + d4] = q;
    }
    #pragma unroll
    for (int off = 16; off; off >>= 1)
        lsum += __shfl_down_sync(0xffffffffu, lsum, off);
    if ((t & 31) == 0) sRed[t >> 5] = lsum;
    __syncthreads();
    if (t == 0) {
        float s = 0.0f;
        #pragma unroll
        for (int wq = 0; wq < 8; ++wq) s += sRed[wq];
        d_loss_partial[blockIdx.x] = s;
    }
}

// ---------------------------------------------------------------------------
// Rescue: re-decide flagged rows with reference-emulated fp32 arithmetic
// ---------------------------------------------------------------------------
__global__ void __launch_bounds__(256)
vq_fix(const float* __restrict__ inputs, float* __restrict__ out) {
    __shared__ float sx[RESCUE_RPB][D_DIM];
    __shared__ float sdist[RESCUE_RPB][K_CODES];
    __shared__ float ssx2[RESCUE_RPB];
    __shared__ int   srow[RESCUE_RPB];
    __shared__ int   sbest[RESCUE_RPB];
    const int t = threadIdx.x;
    const size_t ND = (size_t)N_ROWS * D_DIM;

    const int nf = d_nflag;
    for (int base = blockIdx.x * RESCUE_RPB; base < nf;
         base += gridDim.x * RESCUE_RPB) {
        const int cnt = min(RESCUE_RPB, nf - base);
        __syncthreads();
        if (t < cnt) srow[t] = d_flaglist[base + t];
        __syncthreads();
        for (int r = 0; r < cnt; ++r)
            sx[r][t] = inputs[(size_t)srow[r] * D_DIM + t];
        __syncthreads();
        if (t < cnt) {
            float s = 0.0f;
            for (int d = 0; d < D_DIM; ++d)
                s = __fadd_rn(s, __fmul_rn(sx[t][d], sx[t][d]));
            ssx2[t] = s;
        }
        __syncthreads();

        #pragma unroll
        for (int c = 0; c < 4; ++c) {
            const int k = c * 256 + t;
            const float* e = d_embedT + (size_t)k * D_DIM;
            float acc[RESCUE_RPB];
            #pragma unroll
            for (int r = 0; r < RESCUE_RPB; ++r) acc[r] = 0.0f;
            for (int d = 0; d < D_DIM; ++d) {
                float ev = e[d];
                #pragma unroll
                for (int r = 0; r < RESCUE_RPB; ++r)
                    acc[r] = __fmaf_rn(sx[r][d], ev, acc[r]);
            }
            #pragma unroll
            for (int r = 0; r < RESCUE_RPB; ++r) {
                float twod = __fadd_rn(acc[r], acc[r]);
                float t1   = __fsub_rn(ssx2[r], twod);
                sdist[r][k] = __fadd_rn(t1, d_cnorm[k]);
            }
        }
        __syncthreads();

        if (t < cnt) {
            float best = 3.4e38f; int bk = 0;
            for (int k = 0; k < K_CODES; ++k) {
                float v = sdist[t][k];
                if (v < best) { best = v; bk = k; }
            }
            sbest[t] = bk;
            int oldk = (int)out[ND + 2 + (size_t)srow[t]];
            if (oldk != bk) {
                atomicAdd(&d_counts[bk], 1u);
                atomicAdd(&d_counts[oldk], 0xFFFFFFFFu);
                out[ND + 2 + (size_t)srow[t]] = (float)bk;
            }
        }
        __syncthreads();
        for (int r = 0; r < cnt; ++r)
            out[(size_t)srow[r] * D_DIM + t] =
                d_embedT[(size_t)sbest[r] * D_DIM + t];
    }
}

// ---------------------------------------------------------------------------
// Finalize: loss mean + perplexity
// ---------------------------------------------------------------------------
__global__ void vq_finalize(float* __restrict__ out) {
    __shared__ float sl[1024];
    __shared__ float se[1024];
    int t = threadIdx.x;
    sl[t] = d_loss_partial[t];
    float avg = (float)d_counts[t] * (1.0f / (float)N_ROWS);
    se[t] = avg * logf(avg + 1e-10f);
    __syncthreads();
    for (int s = 512; s; s >>= 1) {
        if (t < s) { sl[t] += sl[t + s]; se[t] += se[t + s]; }
        __syncthreads();
    }
    if (t == 0) {
        const size_t ND = (size_t)N_ROWS * D_DIM;
        out[ND]     = sl[0] / ((float)N_ROWS * (float)D_DIM);
        out[ND + 1] = expf(-se[0]);
    }
}

// ---------------------------------------------------------------------------
extern "C" void kernel_launch(void* const* d_in, const int* in_sizes, int n_in,
                              void* d_out, int out_size) {
    const float* inputs = (const float*)d_in[0];  // [131072, 256]
    const float* embed  = (const float*)d_in[1];  // [256, 1024]
    float* out = (float*)d_out;

    cudaFuncSetAttribute(vq_main_hf,
                         cudaFuncAttributeMaxDynamicSharedMemorySize,
                         SMEM_TOTAL);

    vq_prep<<<8, 128>>>(embed);
    vq_prep_frag16<<<32, 256>>>(embed);
    vq_main_hf<<<N_ROWS / 128, 256, SMEM_TOTAL>>>(inputs, out);
    vq_fix<<<256, 256>>>(inputs, out);
    vq_finalize<<<1, 1024>>>(out);
}

// round 17
// speedup vs baseline: 2.8841x; 2.8841x over previous
#include <cuda_runtime.h>
#include <cuda_bf16.h>
#include <math.h>
#include <stdint.h>

#define K_CODES 1024
#define D_DIM   256
#define N_ROWS  131072
#define ROWS    64            // rows per CTA
#define NCTAS   (N_ROWS / ROWS)   // 2048

#define FLAG_THRESH  0.65f    // bf16 dist-err std ~0.07 -> ~6.5 sigma on diff
#define RESCUE_RPB   8

// ---------------- scratch (device globals; no allocations allowed) ----------
__device__ float        d_cnorm[K_CODES];            // emulated sum(e*e)
__device__ float        d_embedT[K_CODES * D_DIM];   // fp32 codebook, k-major
__device__ uint32_t     d_eBfrag[64 * 2048];         // preformatted B fragments
__device__ unsigned int d_counts[K_CODES];
__device__ float        d_loss_partial[NCTAS];
__device__ int          d_nflag;
__device__ int          d_flaglist[N_ROWS];

__device__ __forceinline__ uint32_t pack_bf2(float a, float b) {
    __nv_bfloat16 ha = __float2bfloat16_rn(a), hb = __float2bfloat16_rn(b);
    return (uint32_t)__bfloat16_as_ushort(ha) |
           ((uint32_t)__bfloat16_as_ushort(hb) << 16);
}

// ---------------------------------------------------------------------------
// Prep 1: emulated codebook norms (ascending-d, mul-then-add), fp32 transpose
// ---------------------------------------------------------------------------
__global__ void vq_prep(const float* __restrict__ embed) {
    int k = blockIdx.x * blockDim.x + threadIdx.x;  // 0..1023
    float s = 0.0f;
    for (int d = 0; d < D_DIM; ++d) {
        float v = embed[(size_t)d * K_CODES + k];
        s = __fadd_rn(s, __fmul_rn(v, v));
        d_embedT[(size_t)k * D_DIM + d] = v;
    }
    d_cnorm[k]  = s;
    d_counts[k] = 0u;
    if (k == 0) d_nflag = 0;
}

// ---------------------------------------------------------------------------
// Prep 2: bf16 B fragments for mma.m16n8k16 (chunk-linear, g = kc*8 + dc)
// ---------------------------------------------------------------------------
__global__ void vq_prep_frag(const float* __restrict__ embed) {
    const int g = blockIdx.x;          // 0..63
    const int kc = g >> 3, dc = g & 7;
    #pragma unroll
    for (int q = 0; q < 4; ++q) {
        int e    = q * 256 + threadIdx.x;   // 0..1023
        int ks   = e >> 9;
        int nt   = (e >> 5) & 15;
        int lane = e & 31;
        int t4   = lane & 3;
        int gq   = lane >> 2;
        int code = kc * 128 + nt * 8 + gq;
        int db   = dc * 32 + ks * 16;
        float e0 = embed[(size_t)(db + 2*t4)     * K_CODES + code];
        float e1 = embed[(size_t)(db + 2*t4 + 1) * K_CODES + code];
        float e2 = embed[(size_t)(db + 2*t4 + 8) * K_CODES + code];
        float e3 = embed[(size_t)(db + 2*t4 + 9) * K_CODES + code];
        uint32_t* dst = d_eBfrag + ((size_t)g * 2048) + (size_t)e * 2;
        dst[0] = pack_bf2(e0, e1);
        dst[1] = pack_bf2(e2, e3);
    }
}

// ---------------------------------------------------------------------------
// SMEM layout (bytes); padded total forces exactly 2 CTAs/SM:
//   [0,4096)      sCn   (1024 f32)
//   [4096,4352)   sIdx  (64 int)
//   [4352,4416)   sRed  (8 f32 + pad)
//   [4416,4928)   sV1   [2][64] f32
//   [4928,5440)   sV2   [2][64] f32
//   [5440,5952)   sI1   [2][64] int
//   [5952,38720)  fragA (4 mt x 16 ks16 x 32 lanes x 4 regs, bf16x2)
//   [38720,55104) fragB (2 bufs x 2048 u32)
// real use 55.1KB; SMEM_TOTAL padded to 77824 (76KB) -> occupancy capped at 2
// ---------------------------------------------------------------------------
#define SM_CN   0
#define SM_IDX  4096
#define SM_RED  4352
#define SM_V1   4416
#define SM_V2   4928
#define SM_I1   5440
#define SM_A    5952
#define SM_B    38720
#define SMEM_TOTAL 77824
#define BSTRIDE 2048        // u32 per fragB buffer

__device__ __forceinline__ void mma_bf16(float c[4], uint32_t a0, uint32_t a1,
                                         uint32_t a2, uint32_t a3,
                                         uint32_t b0, uint32_t b1) {
    asm volatile(
        "mma.sync.aligned.m16n8k16.row.col.f32.bf16.bf16.f32 "
        "{%0,%1,%2,%3}, {%4,%5,%6,%7}, {%8,%9}, {%0,%1,%2,%3};"
        : "+f"(c[0]), "+f"(c[1]), "+f"(c[2]), "+f"(c[3])
        : "r"(a0), "r"(a1), "r"(a2), "r"(a3), "r"(b0), "r"(b1));
}

__device__ __forceinline__ void top2_upd(float& v1, float& v2, int& i1,
                                         float d, int code) {
    if (d < v1)      { v2 = v1; v1 = d; i1 = code; }
    else if (d < v2) { v2 = d; }
}

__global__ void __launch_bounds__(256, 2)
vq_main_mma(const float* __restrict__ inputs, float* __restrict__ out) {
    extern __shared__ char smem[];
    float*    sCn   = (float*)(smem + SM_CN);
    int*      sIdx  = (int*)(smem + SM_IDX);
    float*    sRed  = (float*)(smem + SM_RED);
    float*    sV1   = (float*)(smem + SM_V1);
    float*    sV2   = (float*)(smem + SM_V2);
    int*      sI1   = (int*)(smem + SM_I1);
    uint32_t* fragA = (uint32_t*)(smem + SM_A);
    uint32_t* fragB = (uint32_t*)(smem + SM_B);

    const int t     = threadIdx.x;
    const int w     = t >> 5;
    const int lane  = t & 31;
    const int mt    = w & 3;          // m-tile (16 rows)
    const int half  = w >> 2;         // code half (0: nt 0-7, 1: nt 8-15)
    const int nbase = half * 8;
    const int row0  = blockIdx.x * ROWS;

    for (int i = t; i < K_CODES; i += 256) sCn[i] = d_cnorm[i];

    // ---- Stage A (64 rows x 256 d) -> bf16 fragment-major smem ----
    {
        const float4* in4 = (const float4*)(inputs + (size_t)row0 * D_DIM);
        #pragma unroll
        for (int i = 0; i < 16; ++i) {
            int l   = i * 256 + t;           // 0..4095
            int row = l >> 6;
            int d4  = l & 63;
            float4 v = in4[row * 64 + d4];
            int d    = d4 * 4;
            int mtr  = row >> 4, r16 = row & 15;
            int ks16 = d >> 4;
            int o    = d & 15;
            int reg  = ((o & 8) ? 2 : 0) + ((r16 >= 8) ? 1 : 0);
            int t0   = (o & 7) >> 1;
            uint32_t* p = fragA + ((mtr * 16 + ks16) * 32 + (r16 & 7) * 4 + t0) * 4 + reg;
            p[0] = pack_bf2(v.x, v.y);
            p[4] = pack_bf2(v.z, v.w);
        }
    }

    // ---- Prefetch + stage B chunk 0 ----
    uint4 pv0, pv1;
    {
        const uint4* src = (const uint4*)d_eBfrag;
        pv0 = src[t];
        pv1 = src[t + 256];
        uint4* dst = (uint4*)fragB;
        dst[t]       = pv0;
        dst[t + 256] = pv1;
    }
    __syncthreads();

    float acc[8][4];
    #pragma unroll
    for (int nt = 0; nt < 8; ++nt)
        #pragma unroll
        for (int r = 0; r < 4; ++r) acc[nt][r] = 0.0f;

    float v1a = 3.4e38f, v2a = 3.4e38f; int i1a = 0;   // row mt*16 + lane/4
    float v1b = 3.4e38f, v2b = 3.4e38f; int i1b = 0;   // +8

    const uint32_t* fA = fragA + mt * 2048 + lane * 4;

    for (int g = 0; g < 64; ++g) {          // g = kc*8 + dc
        if (g < 63) {
            const uint4* src = (const uint4*)(d_eBfrag + (size_t)(g + 1) * 2048);
            pv0 = src[t];
            pv1 = src[t + 256];
        }

        // compute chunk g: 2 k16-steps x 8 n-tiles (this warp's code half)
        {
            const uint32_t* fB = fragB + (g & 1) * BSTRIDE + lane * 2;
            #pragma unroll
            for (int ks = 0; ks < 2; ++ks) {
                int ks16 = (g & 7) * 2 + ks;
                uint4 a = *(const uint4*)(fA + ks16 * 128);
                #pragma unroll
                for (int nt = 0; nt < 8; ++nt) {
                    uint2 b = *(const uint2*)(fB + (ks * 16 + nbase + nt) * 64);
                    mma_bf16(acc[nt], a.x, a.y, a.z, a.w, b.x, b.y);
                }
            }
        }

        // epilogue at end of each kc (8 chunks)
        if ((g & 7) == 7) {
            int kc = g >> 3;
            #pragma unroll
            for (int nt = 0; nt < 8; ++nt) {
                int code = kc * 128 + (nbase + nt) * 8 + (lane & 3) * 2;
                float c0 = sCn[code]     - 2.0f * acc[nt][0];
                float c1 = sCn[code + 1] - 2.0f * acc[nt][1];
                float c2 = sCn[code]     - 2.0f * acc[nt][2];
                float c3 = sCn[code + 1] - 2.0f * acc[nt][3];
                top2_upd(v1a, v2a, i1a, c0, code);
                top2_upd(v1a, v2a, i1a, c1, code + 1);
                top2_upd(v1b, v2b, i1b, c2, code);
                top2_upd(v1b, v2b, i1b, c3, code + 1);
                acc[nt][0] = acc[nt][1] = acc[nt][2] = acc[nt][3] = 0.0f;
            }
        }

        if (g < 63) {
            uint4* dst = (uint4*)(fragB + ((g + 1) & 1) * BSTRIDE);
            dst[t]       = pv0;
            dst[t + 256] = pv1;
        }
        __syncthreads();
    }

    // ---- merge top-2 across the 4 lanes sharing each row ----
    #pragma unroll
    for (int off = 1; off < 4; off <<= 1) {
        float w1 = __shfl_down_sync(0xffffffffu, v1a, off, 4);
        int   wi = __shfl_down_sync(0xffffffffu, i1a, off, 4);
        float w2 = __shfl_down_sync(0xffffffffu, v2a, off, 4);
        if (w1 < v1a || (w1 == v1a && wi < i1a)) {
            v2a = fminf(v1a, w2); v1a = w1; i1a = wi;
        } else v2a = fminf(v2a, w1);
        w1 = __shfl_down_sync(0xffffffffu, v1b, off, 4);
        wi = __shfl_down_sync(0xffffffffu, i1b, off, 4);
        w2 = __shfl_down_sync(0xffffffffu, v2b, off, 4);
        if (w1 < v1b || (w1 == v1b && wi < i1b)) {
            v2b = fminf(v1b, w2); v1b = w1; i1b = wi;
        } else v2b = fminf(v2b, w1);
    }

    // publish per-(half,row) top-2 to smem
    if ((lane & 3) == 0) {
        int rA = mt * 16 + (lane >> 2);
        int rB = rA + 8;
        sV1[half * 64 + rA] = v1a;  sV2[half * 64 + rA] = v2a;
        sI1[half * 64 + rA] = i1a;
        sV1[half * 64 + rB] = v1b;  sV2[half * 64 + rB] = v2b;
        sI1[half * 64 + rB] = i1b;
    }
    __syncthreads();

    // ---- final per-row merge of the two code halves (disjoint codes) ----
    const size_t ND = (size_t)N_ROWS * D_DIM;
    if (t < ROWS) {
        float a1 = sV1[t],      a2 = sV2[t];      int ai = sI1[t];
        float b1 = sV1[64 + t], b2 = sV2[64 + t]; int bi = sI1[64 + t];
        float m1, m2; int mi;
        if (b1 < a1 || (b1 == a1 && bi < ai)) {
            m1 = b1; mi = bi; m2 = fminf(b2, a1);
        } else {
            m1 = a1; mi = ai; m2 = fminf(a2, b1);
        }
        sIdx[t] = mi;
        if (m2 - m1 < FLAG_THRESH) {
            int pos = atomicAdd(&d_nflag, 1);
            d_flaglist[pos] = row0 + t;
        }
        atomicAdd(&d_counts[mi], 1u);
        out[ND + 2 + (size_t)(row0 + t)] = (float)mi;
    }
    __syncthreads();

    // ---- quantize (= q exactly) + loss partials ----
    float lsum = 0.0f;
    const float4* inp4 = (const float4*)(inputs + (size_t)row0 * D_DIM);
    float4*       out4 = (float4*)(out + (size_t)row0 * D_DIM);
    const float4* eT4  = (const float4*)d_embedT;
    #pragma unroll 4
    for (int it = 0; it < 16; ++it) {
        int l  = it * 256 + t;
        int r  = l >> 6;
        int d4 = l & 63;
        float4 x = inp4[r * 64 + d4];
        int    k = sIdx[r];
        float4 q = eT4[(size_t)k * 64 + d4];
        float dx = q.x - x.x, dy = q.y - x.y, dz = q.z - x.z, dw = q.w - x.w;
        lsum += dx * dx + dy * dy + dz * dz + dw * dw;
        out4[r * 64 + d4] = q;
    }
    #pragma unroll
    for (int off = 16; off; off >>= 1)
        lsum += __shfl_down_sync(0xffffffffu, lsum, off);
    if ((t & 31) == 0) sRed[t >> 5] = lsum;
    __syncthreads();
    if (t == 0) {
        float s = 0.0f;
        #pragma unroll
        for (int wq = 0; wq < 8; ++wq) s += sRed[wq];
        d_loss_partial[blockIdx.x] = s;
    }
}

// ---------------------------------------------------------------------------
// Rescue: re-decide flagged rows with reference-emulated fp32 arithmetic
// ---------------------------------------------------------------------------
__global__ void __launch_bounds__(256)
vq_fix(const float* __restrict__ inputs, float* __restrict__ out) {
    __shared__ float sx[RESCUE_RPB][D_DIM];
    __shared__ float sdist[RESCUE_RPB][K_CODES];
    __shared__ float ssx2[RESCUE_RPB];
    __shared__ int   srow[RESCUE_RPB];
    __shared__ int   sbest[RESCUE_RPB];
    const int t = threadIdx.x;
    const size_t ND = (size_t)N_ROWS * D_DIM;

    const int nf = d_nflag;
    for (int base = blockIdx.x * RESCUE_RPB; base < nf;
         base += gridDim.x * RESCUE_RPB) {
        const int cnt = min(RESCUE_RPB, nf - base);
        __syncthreads();
        if (t < cnt) srow[t] = d_flaglist[base + t];
        __syncthreads();
        for (int r = 0; r < cnt; ++r)
            sx[r][t] = inputs[(size_t)srow[r] * D_DIM + t];
        __syncthreads();
        if (t < cnt) {
            float s = 0.0f;
            for (int d = 0; d < D_DIM; ++d)
                s = __fadd_rn(s, __fmul_rn(sx[t][d], sx[t][d]));
            ssx2[t] = s;
        }
        __syncthreads();

        #pragma unroll
        for (int c = 0; c < 4; ++c) {
            const int k = c * 256 + t;
            const float* e = d_embedT + (size_t)k * D_DIM;
            float acc[RESCUE_RPB];
            #pragma unroll
            for (int r = 0; r < RESCUE_RPB; ++r) acc[r] = 0.0f;
            for (int d = 0; d < D_DIM; ++d) {
                float ev = e[d];
                #pragma unroll
                for (int r = 0; r < RESCUE_RPB; ++r)
                    acc[r] = __fmaf_rn(sx[r][d], ev, acc[r]);
            }
            #pragma unroll
            for (int r = 0; r < RESCUE_RPB; ++r) {
                float twod = __fadd_rn(acc[r], acc[r]);
                float t1   = __fsub_rn(ssx2[r], twod);
                sdist[r][k] = __fadd_rn(t1, d_cnorm[k]);
            }
        }
        __syncthreads();

        if (t < cnt) {
            float best = 3.4e38f; int bk = 0;
            for (int k = 0; k < K_CODES; ++k) {
                float v = sdist[t][k];
                if (v < best) { best = v; bk = k; }
            }
            sbest[t] = bk;
            int oldk = (int)out[ND + 2 + (size_t)srow[t]];
            if (oldk != bk) {
                atomicAdd(&d_counts[bk], 1u);
                atomicAdd(&d_counts[oldk], 0xFFFFFFFFu);
                out[ND + 2 + (size_t)srow[t]] = (float)bk;
            }
        }
        __syncthreads();
        for (int r = 0; r < cnt; ++r)
            out[(size_t)srow[r] * D_DIM + t] =
                d_embedT[(size_t)sbest[r] * D_DIM + t];
    }
}

// ---------------------------------------------------------------------------
// Finalize: loss mean + perplexity (2048 partials folded 2->1)
// ---------------------------------------------------------------------------
__global__ void vq_finalize(float* __restrict__ out) {
    __shared__ float sl[1024];
    __shared__ float se[1024];
    int t = threadIdx.x;
    sl[t] = d_loss_partial[t] + d_loss_partial[t + 1024];
    float avg = (float)d_counts[t] * (1.0f / (float)N_ROWS);
    se[t] = avg * logf(avg + 1e-10f);
    __syncthreads();
    for (int s = 512; s; s >>= 1) {
        if (t < s) { sl[t] += sl[t + s]; se[t] += se[t + s]; }
        __syncthreads();
    }
    if (t == 0) {
        const size_t ND = (size_t)N_ROWS * D_DIM;
        out[ND]     = sl[0] / ((float)N_ROWS * (float)D_DIM);
        out[ND + 1] = expf(-se[0]);
    }
}

// ---------------------------------------------------------------------------
extern "C" void kernel_launch(void* const* d_in, const int* in_sizes, int n_in,
                              void* d_out, int out_size) {
    const float* inputs = (const float*)d_in[0];  // [131072, 256]
    const float* embed  = (const float*)d_in[1];  // [256, 1024]
    float* out = (float*)d_out;

    cudaFuncSetAttribute(vq_main_mma,
                         cudaFuncAttributeMaxDynamicSharedMemorySize,
                         SMEM_TOTAL);

    vq_prep<<<8, 128>>>(embed);
    vq_prep_frag<<<64, 256>>>(embed);
    vq_main_mma<<<NCTAS, 256, SMEM_TOTAL>>>(inputs, out);
    vq_fix<<<256, 256>>>(inputs, out);
    vq_finalize<<<1, 1024>>>(out);
}